// round 9
// baseline (speedup 1.0000x reference)
#include <cuda_runtime.h>

// Fixed problem shape
#define BATCH 8
#define CDIM  64
#define NPTS  4096
#define KNN   20
#define TM    128    // targets per block == threads per block
#define TC    32     // candidate tile size
#define CAP   16     // per-thread candidate buffer slots
#define NSPLIT 4
#define QN (NPTS / NSPLIT)   // candidates per partial = 1024

// Split-K partial results: [part][k][b*NPTS+n], coalesced in n (~21 MB).
__device__ unsigned long long g_part[NSPLIT][KNN][BATCH * NPTS];

// Packed helpers: fma.rn.f32x2 = two independent rn-rounded fp32 FMAs.
__device__ __forceinline__ void fma2(unsigned long long& acc,
                                     unsigned long long a2,
                                     unsigned long long b2) {
    asm("fma.rn.f32x2 %0, %1, %2, %0;" : "+l"(acc) : "l"(a2), "l"(b2));
}
__device__ __forceinline__ unsigned long long dup2(float a) {
    unsigned long long r;
    asm("mov.b64 %0, {%1, %1};" : "=l"(r) : "f"(a));
    return r;
}
__device__ __forceinline__ void unpack2(unsigned long long v, float& lo, float& hi) {
    asm("mov.b64 {%0, %1}, %2;" : "=f"(lo), "=f"(hi) : "l"(v));
}

// ---------------------------------------------------------------------------
// Kernel 1: identical structure to the 786us round-8 winner; ONLY change is
// the candidate range (quarters instead of halves) for higher occupancy.
// Per-lane distance arithmetic bit-identical to all passing rounds:
//   sequential ascending-c FMA dot & csq; d2 = fma(dot, -2, sqt + csq).
// Top-K: threshold + deferred buffer merge on packed u64 keys
// (d2_bits<<32 | idx) == exact lax.top_k (dist asc, lower idx first).
// ---------------------------------------------------------------------------
__global__ void __launch_bounds__(TM) knn_part(const float* __restrict__ x) {
    __shared__ __align__(16) float sf[CDIM * TC];           // 8 KB tile
    __shared__ __align__(16) float s_csq[TC];
    __shared__ unsigned long long s_top[KNN][TM];           // 20 KB sorted topK
    __shared__ unsigned long long s_buf[CAP][TM];           // 16 KB buffers

    const int b    = blockIdx.y;
    const int part = blockIdx.z;
    const int tid  = threadIdx.x;
    const int tgt  = blockIdx.x * TM + tid;
    const float* xb = x + b * CDIM * NPTS;

    // Target features -> registers; target squared norm (ascending c).
    float tq[CDIM];
    float sqt = 0.f;
#pragma unroll
    for (int c = 0; c < CDIM; c++) {
        tq[c] = xb[c * NPTS + tgt];
        sqt = fmaf(tq[c], tq[c], sqt);
    }

#pragma unroll
    for (int k = 0; k < KNN; k++) s_top[k][tid] = ~0ull;
    unsigned long long thresh = ~0ull;
    int cnt = 0;

    const int cand = tid & (TC - 1);
    const int cgrp = tid >> 5;          // 0..3 (TM = 4*TC)
    const int jbeg = part * QN;

    for (int jt = 0; jt < QN; jt += TC) {
        const int j0 = jbeg + jt;
        __syncthreads();
#pragma unroll
        for (int c = cgrp; c < CDIM; c += 4)
            sf[c * TC + cand] = xb[c * NPTS + j0 + cand];
        __syncthreads();
        if (tid < TC) {                 // csq: ascending c, unchanged order
            float s = 0.f;
#pragma unroll
            for (int c = 0; c < CDIM; c++) {
                float v = sf[c * TC + tid];
                s = fmaf(v, v, s);
            }
            s_csq[tid] = s;
        }
        __syncthreads();

        for (int jg = 0; jg < TC; jg += 8) {
            unsigned long long a01 = 0, a23 = 0, a45 = 0, a67 = 0;
#pragma unroll
            for (int c = 0; c < CDIM; c++) {
                const ulonglong2* rp =
                    reinterpret_cast<const ulonglong2*>(sf + c * TC + jg);
                ulonglong2 v0 = rp[0];          // cands jg..jg+3
                ulonglong2 v1 = rp[1];          // cands jg+4..jg+7
                unsigned long long a2 = dup2(tq[c]);
                fma2(a01, a2, v0.x);
                fma2(a23, a2, v0.y);
                fma2(a45, a2, v1.x);
                fma2(a67, a2, v1.y);
            }
            float dots[8];
            unpack2(a01, dots[0], dots[1]);
            unpack2(a23, dots[2], dots[3]);
            unpack2(a45, dots[4], dots[5]);
            unpack2(a67, dots[6], dots[7]);

            float4 cs0 = *reinterpret_cast<const float4*>(s_csq + jg);
            float4 cs1 = *reinterpret_cast<const float4*>(s_csq + jg + 4);
            float csv[8] = {cs0.x, cs0.y, cs0.z, cs0.w,
                            cs1.x, cs1.y, cs1.z, cs1.w};
#pragma unroll
            for (int u = 0; u < 8; u++) {
                int   j = j0 + jg + u;
                float t = sqt + csv[u];
                float d = fmaf(dots[u], -2.0f, t);   // one final rounding
                unsigned long long key =
                    ((unsigned long long)__float_as_uint(d) << 32) |
                    (unsigned int)j;
                if (j != tgt && key < thresh) {      // cheap append path
                    s_buf[cnt][tid] = key;
                    cnt++;
                }
            }
            // Deferred warp-wide merge; margin 8 so next group can't overflow.
            if (__any_sync(0xffffffffu, cnt > CAP - 8)) {
                for (int i = 0; i < cnt; i++) {
                    unsigned long long kv = s_buf[i][tid];
                    if (kv < s_top[KNN - 1][tid]) {
                        int k = KNN - 1;
                        while (k > 0 && s_top[k - 1][tid] > kv) {
                            s_top[k][tid] = s_top[k - 1][tid];
                            k--;
                        }
                        s_top[k][tid] = kv;
                    }
                }
                cnt = 0;
                thresh = s_top[KNN - 1][tid];
            }
        }
    }

    for (int i = 0; i < cnt; i++) {          // leftovers
        unsigned long long kv = s_buf[i][tid];
        if (kv < s_top[KNN - 1][tid]) {
            int k = KNN - 1;
            while (k > 0 && s_top[k - 1][tid] > kv) {
                s_top[k][tid] = s_top[k - 1][tid];
                k--;
            }
            s_top[k][tid] = kv;
        }
    }

    // Write sorted partial top-20 (coalesced in target index).
    const int col = b * NPTS + tgt;
#pragma unroll
    for (int p = 0; p < KNN; p++)
        g_part[part][p][col] = s_top[p][tid];
}

// ---------------------------------------------------------------------------
// Kernel 2: exact 4-way tournament merge of four sorted top-20 key lists.
// Keys are globally unique (index embedded), so u64 order is total & exact.
// ---------------------------------------------------------------------------
__global__ void __launch_bounds__(64) knn_merge(float* __restrict__ out) {
    __shared__ unsigned long long sm[NSPLIT][KNN][64];  // 40 KB
    const int t   = threadIdx.x;
    const int idx = blockIdx.x * 64 + t;                // 0 .. B*N-1
#pragma unroll
    for (int p = 0; p < KNN; p++)
#pragma unroll
        for (int l = 0; l < NSPLIT; l++)
            sm[l][p][t] = g_part[l][p][idx];            // coalesced

    const int b = idx >> 12;                            // NPTS = 4096
    const int n = idx & (NPTS - 1);
    const int base0 = ((0 * BATCH + b) * NPTS + n) * KNN;
    const int base1 = ((1 * BATCH + b) * NPTS + n) * KNN;
    const float ftgt = (float)n;

    int i0 = 0, i1 = 0, i2 = 0, i3 = 0;
#pragma unroll
    for (int p = 0; p < KNN; p++) {
        unsigned long long v0 = sm[0][i0][t];
        unsigned long long v1 = sm[1][i1][t];
        unsigned long long v2 = sm[2][i2][t];
        unsigned long long v3 = sm[3][i3][t];
        bool l01 = v0 <= v1; unsigned long long m01 = l01 ? v0 : v1;
        bool l23 = v2 <= v3; unsigned long long m23 = l23 ? v2 : v3;
        bool lf  = m01 <= m23;
        unsigned long long m = lf ? m01 : m23;
        i0 += ( lf &&  l01) ? 1 : 0;
        i1 += ( lf && !l01) ? 1 : 0;
        i2 += (!lf &&  l23) ? 1 : 0;
        i3 += (!lf && !l23) ? 1 : 0;
        out[base0 + p] = (float)(int)(unsigned int)(m & 0xffffffffu);
        out[base1 + p] = ftgt;
    }
}

// ---------------------------------------------------------------------------
extern "C" void kernel_launch(void* const* d_in, const int* in_sizes, int n_in,
                              void* d_out, int out_size) {
    (void)in_sizes; (void)n_in; (void)out_size;
    const float* x = (const float*)d_in[0];
    float* out = (float*)d_out;

    dim3 grid(NPTS / TM, BATCH, NSPLIT);    // 32 x 8 x 4 = 1024 CTAs
    knn_part<<<grid, TM>>>(x);
    knn_merge<<<(BATCH * NPTS) / 64, 64>>>(out);
}

// round 10
// speedup vs baseline: 1.1602x; 1.1602x over previous
#include <cuda_runtime.h>

// Fixed problem shape
#define BATCH 8
#define CDIM  64
#define NPTS  4096
#define KNN   20
#define TM    128    // targets per block == threads per block
#define TC    32     // candidate tile size
#define CAP   16     // per-thread candidate buffer slots
#define NSPLIT 2
#define HALF_N (NPTS / NSPLIT)

// Scratch for split-K partial results: [half][k][b*NPTS+n], coalesced in n.
__device__ unsigned long long g_part[NSPLIT][KNN][BATCH * NPTS];

// Packed helpers: fma.rn.f32x2 = two independent rn-rounded fp32 FMAs.
__device__ __forceinline__ void fma2(unsigned long long& acc,
                                     unsigned long long a2,
                                     unsigned long long b2) {
    asm("fma.rn.f32x2 %0, %1, %2, %0;" : "+l"(acc) : "l"(a2), "l"(b2));
}
__device__ __forceinline__ unsigned long long dup2(float a) {
    unsigned long long r;
    asm("mov.b64 %0, {%1, %1};" : "=l"(r) : "f"(a));
    return r;
}
__device__ __forceinline__ void unpack2(unsigned long long v, float& lo, float& hi) {
    asm("mov.b64 {%0, %1}, %2;" : "=f"(lo), "=f"(hi) : "l"(v));
}

// ---------------------------------------------------------------------------
// Kernel 1: the 786us round-8 winner with two scheduling-only changes:
//  (a) __launch_bounds__(TM, 4): grid=512 needs only 4 resident CTAs/SM for a
//      single wave, so give ptxas a 128-reg budget for deeper pipelining.
//  (b) explicit next-channel prefetch in the inner-product loop (bit-identical
//      values; only instruction schedule changes).
// Per-lane distance arithmetic bit-identical to all passing rounds:
//   sequential ascending-c FMA dot & csq; d2 = fma(dot, -2, sqt + csq).
// Top-K: threshold + deferred buffer merge on packed u64 keys
// (d2_bits<<32 | idx) == exact lax.top_k (dist asc, lower idx first).
// ---------------------------------------------------------------------------
__global__ void __launch_bounds__(TM, 4) knn_half(const float* __restrict__ x) {
    __shared__ __align__(16) float sf[CDIM * TC];           // 8 KB tile
    __shared__ __align__(16) float s_csq[TC];
    __shared__ unsigned long long s_top[KNN][TM];           // 20 KB sorted topK
    __shared__ unsigned long long s_buf[CAP][TM];           // 16 KB buffers

    const int b    = blockIdx.y;
    const int half = blockIdx.z;
    const int tid  = threadIdx.x;
    const int tgt  = blockIdx.x * TM + tid;
    const float* xb = x + b * CDIM * NPTS;

    // Target features -> registers; target squared norm (ascending c).
    float tq[CDIM];
    float sqt = 0.f;
#pragma unroll
    for (int c = 0; c < CDIM; c++) {
        tq[c] = xb[c * NPTS + tgt];
        sqt = fmaf(tq[c], tq[c], sqt);
    }

#pragma unroll
    for (int k = 0; k < KNN; k++) s_top[k][tid] = ~0ull;
    unsigned long long thresh = ~0ull;
    int cnt = 0;

    const int cand = tid & (TC - 1);
    const int cgrp = tid >> 5;          // 0..3 (TM = 4*TC)
    const int jbeg = half * HALF_N;

    for (int jt = 0; jt < HALF_N; jt += TC) {
        const int j0 = jbeg + jt;
        __syncthreads();
#pragma unroll
        for (int c = cgrp; c < CDIM; c += 4)
            sf[c * TC + cand] = xb[c * NPTS + j0 + cand];
        __syncthreads();
        if (tid < TC) {                 // csq: ascending c, unchanged order
            float s = 0.f;
#pragma unroll
            for (int c = 0; c < CDIM; c++) {
                float v = sf[c * TC + tid];
                s = fmaf(v, v, s);
            }
            s_csq[tid] = s;
        }
        __syncthreads();

        for (int jg = 0; jg < TC; jg += 8) {
            unsigned long long a01 = 0, a23 = 0, a45 = 0, a67 = 0;
            const ulonglong2* rp0 =
                reinterpret_cast<const ulonglong2*>(sf + jg);
            // Explicit 1-channel-ahead prefetch (schedule-only change).
            ulonglong2 p0 = rp0[0];
            ulonglong2 p1 = rp0[1];
#pragma unroll
            for (int c = 0; c < CDIM; c++) {
                ulonglong2 n0, n1;
                if (c < CDIM - 1) {
                    const ulonglong2* rn =
                        reinterpret_cast<const ulonglong2*>(sf + (c + 1) * TC + jg);
                    n0 = rn[0];
                    n1 = rn[1];
                }
                unsigned long long a2 = dup2(tq[c]);
                fma2(a01, a2, p0.x);
                fma2(a23, a2, p0.y);
                fma2(a45, a2, p1.x);
                fma2(a67, a2, p1.y);
                if (c < CDIM - 1) { p0 = n0; p1 = n1; }
            }
            float dots[8];
            unpack2(a01, dots[0], dots[1]);
            unpack2(a23, dots[2], dots[3]);
            unpack2(a45, dots[4], dots[5]);
            unpack2(a67, dots[6], dots[7]);

            float4 cs0 = *reinterpret_cast<const float4*>(s_csq + jg);
            float4 cs1 = *reinterpret_cast<const float4*>(s_csq + jg + 4);
            float csv[8] = {cs0.x, cs0.y, cs0.z, cs0.w,
                            cs1.x, cs1.y, cs1.z, cs1.w};
#pragma unroll
            for (int u = 0; u < 8; u++) {
                int   j = j0 + jg + u;
                float t = sqt + csv[u];
                float d = fmaf(dots[u], -2.0f, t);   // one final rounding
                unsigned long long key =
                    ((unsigned long long)__float_as_uint(d) << 32) |
                    (unsigned int)j;
                if (j != tgt && key < thresh) {      // cheap append path
                    s_buf[cnt][tid] = key;
                    cnt++;
                }
            }
            // Deferred warp-wide merge; margin 8 so next group can't overflow.
            if (__any_sync(0xffffffffu, cnt > CAP - 8)) {
                for (int i = 0; i < cnt; i++) {
                    unsigned long long kv = s_buf[i][tid];
                    if (kv < s_top[KNN - 1][tid]) {
                        int k = KNN - 1;
                        while (k > 0 && s_top[k - 1][tid] > kv) {
                            s_top[k][tid] = s_top[k - 1][tid];
                            k--;
                        }
                        s_top[k][tid] = kv;
                    }
                }
                cnt = 0;
                thresh = s_top[KNN - 1][tid];
            }
        }
    }

    for (int i = 0; i < cnt; i++) {          // leftovers
        unsigned long long kv = s_buf[i][tid];
        if (kv < s_top[KNN - 1][tid]) {
            int k = KNN - 1;
            while (k > 0 && s_top[k - 1][tid] > kv) {
                s_top[k][tid] = s_top[k - 1][tid];
                k--;
            }
            s_top[k][tid] = kv;
        }
    }

    // Write sorted partial top-20 (coalesced in target index).
    const int col = b * NPTS + tgt;
#pragma unroll
    for (int p = 0; p < KNN; p++)
        g_part[half][p][col] = s_top[p][tid];
}

// ---------------------------------------------------------------------------
// Kernel 2: exact 2-pointer merge of the two sorted per-half top-20 lists.
// ---------------------------------------------------------------------------
__global__ void __launch_bounds__(128) knn_merge(float* __restrict__ out) {
    __shared__ unsigned long long sa[KNN][128];
    __shared__ unsigned long long sb[KNN][128];
    const int t   = threadIdx.x;
    const int idx = blockIdx.x * 128 + t;      // 0 .. B*N-1
#pragma unroll
    for (int p = 0; p < KNN; p++) {
        sa[p][t] = g_part[0][p][idx];          // coalesced
        sb[p][t] = g_part[1][p][idx];
    }
    const int b = idx >> 12;                   // NPTS = 4096
    const int n = idx & (NPTS - 1);
    const int base0 = ((0 * BATCH + b) * NPTS + n) * KNN;
    const int base1 = ((1 * BATCH + b) * NPTS + n) * KNN;
    const float ftgt = (float)n;

    int ia = 0, ib = 0;
#pragma unroll
    for (int p = 0; p < KNN; p++) {
        unsigned long long va = sa[ia][t];
        unsigned long long vb = sb[ib][t];
        bool ta = va < vb;                     // u64 order == exact key order
        unsigned long long v = ta ? va : vb;
        ia += ta ? 1 : 0;
        ib += ta ? 0 : 1;
        out[base0 + p] = (float)(int)(unsigned int)(v & 0xffffffffu);
        out[base1 + p] = ftgt;
    }
}

// ---------------------------------------------------------------------------
extern "C" void kernel_launch(void* const* d_in, const int* in_sizes, int n_in,
                              void* d_out, int out_size) {
    (void)in_sizes; (void)n_in; (void)out_size;
    const float* x = (const float*)d_in[0];
    float* out = (float*)d_out;

    dim3 grid(NPTS / TM, BATCH, NSPLIT);       // 32 x 8 x 2 = 512 CTAs
    knn_half<<<grid, TM>>>(x);
    knn_merge<<<(BATCH * NPTS) / 128, 128>>>(out);
}

// round 11
// speedup vs baseline: 1.1764x; 1.0140x over previous
#include <cuda_runtime.h>
#include <cstdint>

// Fixed problem shape
#define BATCH 8
#define CDIM  64
#define NPTS  4096
#define KNN   20
#define TM    128    // targets per block == threads per block
#define TC    32     // candidate tile size
#define CAP   10     // per-thread candidate buffer slots (trigger at cnt>2)
#define NSPLIT 2
#define HALF_N (NPTS / NSPLIT)
#define TROW  (CDIM + 1)          // 64 channel rows + 1 csq row

// Cross-kernel scratch (device globals are legal; no allocations).
__device__ float g_csq[BATCH * NPTS];
__device__ unsigned long long g_part[NSPLIT][KNN][BATCH * NPTS];

// Packed helpers: fma.rn.f32x2 = two independent rn-rounded fp32 FMAs.
__device__ __forceinline__ void fma2(unsigned long long& acc,
                                     unsigned long long a2,
                                     unsigned long long b2) {
    asm("fma.rn.f32x2 %0, %1, %2, %0;" : "+l"(acc) : "l"(a2), "l"(b2));
}
__device__ __forceinline__ unsigned long long dup2(float a) {
    unsigned long long r;
    asm("mov.b64 %0, {%1, %1};" : "=l"(r) : "f"(a));
    return r;
}
__device__ __forceinline__ void unpack2(unsigned long long v, float& lo, float& hi) {
    asm("mov.b64 {%0, %1}, %2;" : "=f"(lo), "=f"(hi) : "l"(v));
}
// cp.async helpers (16B chunks).
__device__ __forceinline__ void cp_async16(const float* smem_dst, const float* gmem_src) {
    uint32_t s = (uint32_t)__cvta_generic_to_shared(smem_dst);
    asm volatile("cp.async.ca.shared.global [%0], [%1], 16;" :: "r"(s), "l"(gmem_src));
}
#define CP_COMMIT() asm volatile("cp.async.commit_group;" ::: "memory")
#define CP_WAIT0()  asm volatile("cp.async.wait_group 0;" ::: "memory")

// ---------------------------------------------------------------------------
// Prologue: g_csq[b][n] = sum_c x[b][c][n]^2, ascending-c sequential FMA —
// bit-identical to the per-tile csq it replaces (same values, same order).
// ---------------------------------------------------------------------------
__global__ void __launch_bounds__(256) sq_all(const float* __restrict__ x) {
    int idx = blockIdx.x * 256 + threadIdx.x;   // 0 .. B*N-1
    int b = idx >> 12;
    int n = idx & (NPTS - 1);
    const float* xb = x + b * CDIM * NPTS;
    float s = 0.f;
#pragma unroll
    for (int c = 0; c < CDIM; c++) {
        float v = xb[c * NPTS + n];             // coalesced
        s = fmaf(v, v, s);
    }
    g_csq[idx] = s;
}

// ---------------------------------------------------------------------------
// Kernel 1: compute/top-K identical to the 786us round-8 winner. Changes:
//  - csq comes from g_csq (staged with the tile) — no serial csq section.
//  - tiles double-buffered via cp.async: copy(t+1) overlaps compute(t);
//    ONE __syncthreads per tile.
// Per-lane distance arithmetic bit-identical to all passing rounds:
//   sequential ascending-c FMA dot & csq; d2 = fma(dot, -2, sqt + csq).
// Top-K: threshold + deferred buffer merge on packed u64 keys
// (d2_bits<<32 | idx) == exact lax.top_k (dist asc, lower idx first).
// ---------------------------------------------------------------------------
__global__ void __launch_bounds__(TM, 4) knn_half(const float* __restrict__ x) {
    __shared__ __align__(16) float s_tile[2][TROW * TC];    // 2 x 8.125 KB
    __shared__ unsigned long long s_top[KNN][TM];           // 20 KB sorted topK
    __shared__ unsigned long long s_buf[CAP][TM];           // 10 KB buffers

    const int b    = blockIdx.y;
    const int half = blockIdx.z;
    const int tid  = threadIdx.x;
    const int tgt  = blockIdx.x * TM + tid;
    const float* xb = x + b * CDIM * NPTS;
    const float* cq = g_csq + b * NPTS;
    const int jbeg = half * HALF_N;
    const int NT   = HALF_N / TC;               // 64 tiles

    // Target features -> registers; target squared norm (ascending c).
    float tq[CDIM];
    float sqt = 0.f;
#pragma unroll
    for (int c = 0; c < CDIM; c++) {
        tq[c] = xb[c * NPTS + tgt];
        sqt = fmaf(tq[c], tq[c], sqt);
    }

#pragma unroll
    for (int k = 0; k < KNN; k++) s_top[k][tid] = ~0ull;
    unsigned long long thresh = ~0ull;
    int cnt = 0;

    // Stage one tile (64 channel rows + csq row) into buffer nb.
    auto stage = [&](int nb, int j0) {
        float* dst = s_tile[nb];
#pragma unroll
        for (int k = 0; k < 4; k++) {
            int cid = tid * 4 + k;              // 0..511 chunk id
            int c = cid >> 3, i = cid & 7;
            cp_async16(dst + c * TC + i * 4, xb + c * NPTS + j0 + i * 4);
        }
        if (tid < 8)
            cp_async16(dst + CDIM * TC + tid * 4, cq + j0 + tid * 4);
        CP_COMMIT();
    };

    stage(0, jbeg);                             // preload tile 0

    for (int t = 0; t < NT; t++) {
        const int cur = t & 1;
        const int j0  = jbeg + t * TC;
        CP_WAIT0();                             // tile t fully arrived
        __syncthreads();                        // visible to all; prev compute done
        if (t + 1 < NT) stage(cur ^ 1, j0 + TC);// overlaps compute below

        const float* sf  = s_tile[cur];
        const float* csq = sf + CDIM * TC;

        for (int jg = 0; jg < TC; jg += 8) {
            unsigned long long a01 = 0, a23 = 0, a45 = 0, a67 = 0;
#pragma unroll
            for (int c = 0; c < CDIM; c++) {
                const ulonglong2* rp =
                    reinterpret_cast<const ulonglong2*>(sf + c * TC + jg);
                ulonglong2 v0 = rp[0];          // cands jg..jg+3
                ulonglong2 v1 = rp[1];          // cands jg+4..jg+7
                unsigned long long a2 = dup2(tq[c]);
                fma2(a01, a2, v0.x);
                fma2(a23, a2, v0.y);
                fma2(a45, a2, v1.x);
                fma2(a67, a2, v1.y);
            }
            float dots[8];
            unpack2(a01, dots[0], dots[1]);
            unpack2(a23, dots[2], dots[3]);
            unpack2(a45, dots[4], dots[5]);
            unpack2(a67, dots[6], dots[7]);

            float4 cs0 = *reinterpret_cast<const float4*>(csq + jg);
            float4 cs1 = *reinterpret_cast<const float4*>(csq + jg + 4);
            float csv[8] = {cs0.x, cs0.y, cs0.z, cs0.w,
                            cs1.x, cs1.y, cs1.z, cs1.w};
#pragma unroll
            for (int u = 0; u < 8; u++) {
                int   j = j0 + jg + u;
                float ts = sqt + csv[u];
                float d  = fmaf(dots[u], -2.0f, ts);  // one final rounding
                unsigned long long key =
                    ((unsigned long long)__float_as_uint(d) << 32) |
                    (unsigned int)j;
                if (j != tgt && key < thresh) {       // cheap append path
                    s_buf[cnt][tid] = key;
                    cnt++;
                }
            }
            // Deferred warp-wide merge; margin 8 (max appends per group)
            // guarantees cnt <= CAP before the next check.
            if (__any_sync(0xffffffffu, cnt > CAP - 8)) {
                for (int i = 0; i < cnt; i++) {
                    unsigned long long kv = s_buf[i][tid];
                    if (kv < s_top[KNN - 1][tid]) {
                        int k = KNN - 1;
                        while (k > 0 && s_top[k - 1][tid] > kv) {
                            s_top[k][tid] = s_top[k - 1][tid];
                            k--;
                        }
                        s_top[k][tid] = kv;
                    }
                }
                cnt = 0;
                thresh = s_top[KNN - 1][tid];
            }
        }
        __syncthreads();                        // done reading buf[cur] before
                                                // iter t+1 overwrites it
    }

    for (int i = 0; i < cnt; i++) {             // leftovers
        unsigned long long kv = s_buf[i][tid];
        if (kv < s_top[KNN - 1][tid]) {
            int k = KNN - 1;
            while (k > 0 && s_top[k - 1][tid] > kv) {
                s_top[k][tid] = s_top[k - 1][tid];
                k--;
            }
            s_top[k][tid] = kv;
        }
    }

    // Write sorted partial top-20 (coalesced in target index).
    const int col = b * NPTS + tgt;
#pragma unroll
    for (int p = 0; p < KNN; p++)
        g_part[half][p][col] = s_top[p][tid];
}

// ---------------------------------------------------------------------------
// Kernel 2: exact 2-pointer merge of the two sorted per-half top-20 lists.
// ---------------------------------------------------------------------------
__global__ void __launch_bounds__(128) knn_merge(float* __restrict__ out) {
    __shared__ unsigned long long sa[KNN][128];
    __shared__ unsigned long long sb[KNN][128];
    const int t   = threadIdx.x;
    const int idx = blockIdx.x * 128 + t;       // 0 .. B*N-1
#pragma unroll
    for (int p = 0; p < KNN; p++) {
        sa[p][t] = g_part[0][p][idx];           // coalesced
        sb[p][t] = g_part[1][p][idx];
    }
    const int b = idx >> 12;                    // NPTS = 4096
    const int n = idx & (NPTS - 1);
    const int base0 = ((0 * BATCH + b) * NPTS + n) * KNN;
    const int base1 = ((1 * BATCH + b) * NPTS + n) * KNN;
    const float ftgt = (float)n;

    int ia = 0, ib = 0;
#pragma unroll
    for (int p = 0; p < KNN; p++) {
        unsigned long long va = sa[ia][t];
        unsigned long long vb = sb[ib][t];
        bool ta = va < vb;                      // u64 order == exact key order
        unsigned long long v = ta ? va : vb;
        ia += ta ? 1 : 0;
        ib += ta ? 0 : 1;
        out[base0 + p] = (float)(int)(unsigned int)(v & 0xffffffffu);
        out[base1 + p] = ftgt;
    }
}

// ---------------------------------------------------------------------------
extern "C" void kernel_launch(void* const* d_in, const int* in_sizes, int n_in,
                              void* d_out, int out_size) {
    (void)in_sizes; (void)n_in; (void)out_size;
    const float* x = (const float*)d_in[0];
    float* out = (float*)d_out;

    sq_all<<<(BATCH * NPTS) / 256, 256>>>(x);
    dim3 grid(NPTS / TM, BATCH, NSPLIT);        // 32 x 8 x 2 = 512 CTAs
    knn_half<<<grid, TM>>>(x);
    knn_merge<<<(BATCH * NPTS) / 128, 128>>>(out);
}